// round 15
// baseline (speedup 1.0000x reference)
#include <cuda_runtime.h>
#include <math.h>

// ---------------------------------------------------------------------------
// TextEmbedderLETS on GB300 — R15: occupancy experiment. SPLITS 28, 8 CTAs/SM
//   (1140 CTAs, ~62 warps/SM = 96% occ, still one wave <= 1184).
//   R11..R14 all plateau at 6.6-6.9 TB/s ~= LTS cap x clock; the only
//   untested lever is warp count (all prior configs <= 48 warps/SM).
//   Hybrid static+steal retained from R14 (kernel-best 100.9us @ 84.7%).
// ---------------------------------------------------------------------------

#define BD 256
#define B_SZ 8
#define C_SZ 7
#define T_SZ 45
#define D_SZ 5120
#define D4_SZ (D_SZ / 4)          // 1280
#define S_SZ 4096
#define SPLITS 28                 // CTAs per group (partial slots)
#define CHUNK_ROWS 8
#define STATIC_CHUNKS_PER_CTA 13
#define STATIC_ROWS_PER_CTA (STATIC_CHUNKS_PER_CTA * CHUNK_ROWS)   // 104
#define STATIC_ROWS (SPLITS * STATIC_ROWS_PER_CTA)                 // 2912
#define STEAL_CHUNKS ((S_SZ - STATIC_ROWS) / CHUNK_ROWS)           // 148
#define SERIES_CTAS (D_SZ / BD)           // 20
#define STREAM_CTAS (5 * B_SZ * SPLITS)   // 1120
#define TOTAL_CTAS (SERIES_CTAS + STREAM_CTAS) // 1140 <= 1184 (148*8): one wave
#define N_GROUPS (5 * B_SZ)               // 40

__device__ float4   g_part[SPLITS * B_SZ * D4_SZ];    // partial sums (4.59 MB)
__device__ float    g_emb [B_SZ * D_SZ];              // un-normalized projection
__device__ float    g_ssq_part[SERIES_CTAS * B_SZ];   // per-CTA per-batch sumsq
__device__ unsigned g_next[N_GROUPS];                 // per-group steal cursor
__device__ unsigned g_cnt[N_GROUPS];                  // per-group arrival counters
__device__ unsigned g_series_done;                    // == 20 when series done
__device__ unsigned g_fin;                            // finisher count (reset)

__device__ __forceinline__ unsigned atom_add_acqrel_gpu(unsigned* p, unsigned v) {
    unsigned old;
    asm volatile("atom.add.acq_rel.gpu.u32 %0, [%1], %2;"
                 : "=r"(old) : "l"(p), "r"(v) : "memory");
    return old;
}
__device__ __forceinline__ unsigned ld_acquire_gpu(const unsigned* p) {
    unsigned v;
    asm volatile("ld.acquire.gpu.u32 %0, [%1];" : "=r"(v) : "l"(p) : "memory");
    return v;
}

__global__ __launch_bounds__(BD, 8) void fused_kernel(
    const float* __restrict__ hs,
    const float* __restrict__ x,
    const float* __restrict__ W,
    const float* __restrict__ bias,
    float* __restrict__ out_fused,
    float* __restrict__ out_xnorm)
{
    const int cta = blockIdx.x;
    const int tid = threadIdx.x;

    if (cta < SERIES_CTAS) {
        // ================= series branch (20 CTAs) ==========================
        const int sid = cta;
        const int d   = sid * BD + tid;

        __shared__ float sx[B_SZ * C_SZ * T_SZ];
        __shared__ float smn[B_SZ * C_SZ], smx[B_SZ * C_SZ];
        __shared__ float s_sm[B_SZ * T_SZ];
        __shared__ float sred[8][B_SZ];

        const int TOT = B_SZ * C_SZ * T_SZ;       // 2520
        for (int i = tid; i < TOT; i += BD) sx[i] = x[i];
        __syncthreads();

        if (tid < B_SZ * C_SZ) {
            const float* row = sx + tid * T_SZ;
            float mn = row[0], mx = row[0];
            #pragma unroll
            for (int t = 1; t < T_SZ; t++) {
                float v = row[t];
                mn = fminf(mn, v); mx = fmaxf(mx, v);
            }
            smn[tid] = mn; smx[tid] = mx;
        }
        __syncthreads();

        if (sid == 0) {
            for (int i = tid; i < TOT; i += BD) {
                int bc = i / T_SZ;
                float v = sx[i], mn = smn[bc], mx = smx[bc];
                out_xnorm[i] = (mx > mn) ? (v - mn) / (mx - mn) : v;
            }
        }

        for (int i = tid; i < B_SZ * T_SZ; i += BD) {
            int b = i / T_SZ, t = i % T_SZ;
            float s = 0.f;
            #pragma unroll
            for (int c = 0; c < C_SZ; c++)
                s += sx[(b * C_SZ + c) * T_SZ + t];
            s_sm[i] = s * (1.0f / (float)C_SZ);
        }
        __syncthreads();

        const float bv = bias[d];
        const int warp = tid >> 5, lane = tid & 31;

        #pragma unroll
        for (int g = 0; g < 2; g++) {
            float acc0 = bv, acc1 = bv, acc2 = bv, acc3 = bv;
            const float* m0 = s_sm + (g * 4 + 0) * T_SZ;
            const float* m1 = s_sm + (g * 4 + 1) * T_SZ;
            const float* m2 = s_sm + (g * 4 + 2) * T_SZ;
            const float* m3 = s_sm + (g * 4 + 3) * T_SZ;
            #pragma unroll
            for (int t = 0; t < T_SZ; t++) {
                const float w = W[(size_t)t * D_SZ + d];
                acc0 = fmaf(m0[t], w, acc0);
                acc1 = fmaf(m1[t], w, acc1);
                acc2 = fmaf(m2[t], w, acc2);
                acc3 = fmaf(m3[t], w, acc3);
            }
            g_emb[(size_t)(g * 4 + 0) * D_SZ + d] = acc0;
            g_emb[(size_t)(g * 4 + 1) * D_SZ + d] = acc1;
            g_emb[(size_t)(g * 4 + 2) * D_SZ + d] = acc2;
            g_emb[(size_t)(g * 4 + 3) * D_SZ + d] = acc3;

            const float sq[4] = {acc0 * acc0, acc1 * acc1, acc2 * acc2, acc3 * acc3};
            #pragma unroll
            for (int j = 0; j < 4; j++) {
                float v = sq[j];
                #pragma unroll
                for (int off = 16; off; off >>= 1)
                    v += __shfl_xor_sync(0xffffffffu, v, off);
                if (lane == 0) sred[warp][g * 4 + j] = v;
            }
            __syncthreads();
            if (tid < 4) {
                int b = g * 4 + tid;
                float tot = 0.f;
                #pragma unroll
                for (int w2 = 0; w2 < 8; w2++) tot += sred[w2][b];
                g_ssq_part[sid * B_SZ + b] = tot;
            }
            __syncthreads();
        }

        if (tid == 0) atom_add_acqrel_gpu(&g_series_done, 1u);
    } else {
        // ================= streaming CTAs (1120, hybrid static+steal) =======
        const int scta   = cta - SERIES_CTAS;
        const int group  = scta % N_GROUPS;       // (b, dchunk)
        const int rank   = scta / N_GROUPS;       // 0..27: partial slot
        const int dchunk = group % 5;
        const int b      = group / 5;
        const int d4     = dchunk * BD + tid;

        const float4* base = reinterpret_cast<const float4*>(hs)
                           + (size_t)b * S_SZ * D4_SZ + d4;

        float4 a0 = make_float4(0.f, 0.f, 0.f, 0.f);
        float4 a1 = make_float4(0.f, 0.f, 0.f, 0.f);

        // ---- phase 1: static 104 rows, pure stream (zero sync) -------------
        {
            const float4* p = base + (size_t)(rank * STATIC_ROWS_PER_CTA) * D4_SZ;
            #pragma unroll 4
            for (int r = 0; r < STATIC_ROWS_PER_CTA; r += 2) {
                float4 v0 = __ldcs(p + (size_t)(r + 0) * D4_SZ);
                float4 v1 = __ldcs(p + (size_t)(r + 1) * D4_SZ);
                a0.x += v0.x; a0.y += v0.y; a0.z += v0.z; a0.w += v0.w;
                a1.x += v1.x; a1.y += v1.y; a1.z += v1.z; a1.w += v1.w;
            }
        }

        // ---- phase 2: steal remaining 148 chunks (absorbs spread) ----------
        {
            __shared__ unsigned s_next[2];
            if (tid == 0) s_next[0] = atomicAdd(&g_next[group], 1u);
            __syncthreads();

            int par = 0;
            for (;;) {
                const unsigned ck = s_next[par];
                if (ck >= STEAL_CHUNKS) break;
                if (tid == 0) s_next[par ^ 1] = atomicAdd(&g_next[group], 1u);

                const float4* p = base
                    + (size_t)(STATIC_ROWS + ck * CHUNK_ROWS) * D4_SZ;
                #pragma unroll
                for (int r = 0; r < CHUNK_ROWS; r += 2) {
                    float4 v0 = __ldcs(p + (size_t)(r + 0) * D4_SZ);
                    float4 v1 = __ldcs(p + (size_t)(r + 1) * D4_SZ);
                    a0.x += v0.x; a0.y += v0.y; a0.z += v0.z; a0.w += v0.w;
                    a1.x += v1.x; a1.y += v1.y; a1.z += v1.z; a1.w += v1.w;
                }
                __syncthreads();
                par ^= 1;
            }
        }

        float4 out;
        out.x = a0.x + a1.x; out.y = a0.y + a1.y;
        out.z = a0.z + a1.z; out.w = a0.w + a1.w;
        g_part[((size_t)rank * B_SZ + b) * D4_SZ + d4] = out;

        // arrival: one barrier orders all warps' STGs; thread 0 release-bumps
        __shared__ bool s_last;
        __syncthreads();
        if (tid == 0) {
            unsigned old = atom_add_acqrel_gpu(&g_cnt[group], 1u);
            s_last = (old == SPLITS - 1);
        }
        __syncthreads();

        if (s_last) {
            // ---- finisher: reduce 28 partials for this (b, dchunk) --------
            __shared__ float s_inv;
            if (tid == 0) {
                while (ld_acquire_gpu(&g_series_done) < SERIES_CTAS)
                    __nanosleep(64);
                float ssq = 0.f;
                #pragma unroll
                for (int s = 0; s < SERIES_CTAS; s++)
                    ssq += __ldcg(&g_ssq_part[s * B_SZ + b]);
                s_inv = 1.0f / fmaxf(sqrtf(ssq), 1e-12f);
            }
            __syncthreads();

            const float4* gp = g_part + (size_t)b * D4_SZ + d4;
            float4 acc = make_float4(0.f, 0.f, 0.f, 0.f);
            #pragma unroll
            for (int rr = 0; rr < SPLITS; rr++) {
                float4 v = __ldcg(gp + (size_t)rr * (B_SZ * D4_SZ));
                acc.x += v.x; acc.y += v.y; acc.z += v.z; acc.w += v.w;
            }

            const float inv  = s_inv;
            const float invS = 1.0f / (float)S_SZ;
            const float* e = g_emb + (size_t)b * D_SZ + (size_t)d4 * 4;
            float e0 = __ldcg(e + 0), e1 = __ldcg(e + 1);
            float e2 = __ldcg(e + 2), e3 = __ldcg(e + 3);

            float4 o;
            o.x = fmaf(e0, inv, acc.x * invS);
            o.y = fmaf(e1, inv, acc.y * invS);
            o.z = fmaf(e2, inv, acc.z * invS);
            o.w = fmaf(e3, inv, acc.w * invS);
            reinterpret_cast<float4*>(out_fused)[(size_t)b * D4_SZ + d4] = o;

            // reset scratch for the next graph replay
            __syncthreads();
            if (tid == 0) {
                g_cnt[group]  = 0u;
                g_next[group] = 0u;
                unsigned f = atom_add_acqrel_gpu(&g_fin, 1u);
                if (f == N_GROUPS - 1) {      // globally last finisher
                    g_series_done = 0u;
                    g_fin = 0u;
                }
            }
        }
    }
}

// ============================================================================
extern "C" void kernel_launch(void* const* d_in, const int* in_sizes, int n_in,
                              void* d_out, int out_size)
{
    const float* x    = (const float*)d_in[0];
    const float* hs   = (const float*)d_in[1];
    const float* W    = (const float*)d_in[2];
    const float* bias = (const float*)d_in[3];

    float* out_fused = (float*)d_out;                       // [B, D]
    float* out_xnorm = (float*)d_out + (size_t)B_SZ * D_SZ; // [B, C, T]

    fused_kernel<<<TOTAL_CTAS, BD>>>(hs, x, W, bias, out_fused, out_xnorm);
}

// round 16
// speedup vs baseline: 1.0658x; 1.0658x over previous
#include <cuda_runtime.h>
#include <math.h>

// ---------------------------------------------------------------------------
// TextEmbedderLETS on GB300 — R16: R14 hybrid with rebalanced static/steal.
//   R15 closed the occupancy question: >48 warps/SM does not raise the
//   ~6.9TB/s effective ceiling (it regressed to 80.5%). Remaining budget:
//   steal phase (84.2% eff) was 30% of work but only needs to cover ~8us of
//   static spread. Rebalance: static 168 rows (82.6%), steal 71 chunks
//   (14.5%, ~13.5us buffer > 8us spread). Everything else = R14.
// ---------------------------------------------------------------------------

#define BD 256
#define B_SZ 8
#define C_SZ 7
#define T_SZ 45
#define D_SZ 5120
#define D4_SZ (D_SZ / 4)          // 1280
#define S_SZ 4096
#define SPLITS 21                 // CTAs per group (partial slots)
#define CHUNK_ROWS 8
#define STATIC_CHUNKS_PER_CTA 21
#define STATIC_ROWS_PER_CTA (STATIC_CHUNKS_PER_CTA * CHUNK_ROWS)   // 168
#define STATIC_ROWS (SPLITS * STATIC_ROWS_PER_CTA)                 // 3528
#define STEAL_CHUNKS ((S_SZ - STATIC_ROWS) / CHUNK_ROWS)           // 71
#define SERIES_CTAS (D_SZ / BD)           // 20
#define STREAM_CTAS (5 * B_SZ * SPLITS)   // 840
#define TOTAL_CTAS (SERIES_CTAS + STREAM_CTAS) // 860 < 888 (148*6)
#define N_GROUPS (5 * B_SZ)               // 40

__device__ float4   g_part[SPLITS * B_SZ * D4_SZ];    // partial sums (3.44 MB)
__device__ float    g_emb [B_SZ * D_SZ];              // un-normalized projection
__device__ float    g_ssq_part[SERIES_CTAS * B_SZ];   // per-CTA per-batch sumsq
__device__ unsigned g_next[N_GROUPS];                 // per-group steal cursor
__device__ unsigned g_cnt[N_GROUPS];                  // per-group arrival counters
__device__ unsigned g_series_done;                    // == 20 when series done
__device__ unsigned g_fin;                            // finisher count (reset)

__device__ __forceinline__ unsigned atom_add_acqrel_gpu(unsigned* p, unsigned v) {
    unsigned old;
    asm volatile("atom.add.acq_rel.gpu.u32 %0, [%1], %2;"
                 : "=r"(old) : "l"(p), "r"(v) : "memory");
    return old;
}
__device__ __forceinline__ unsigned ld_acquire_gpu(const unsigned* p) {
    unsigned v;
    asm volatile("ld.acquire.gpu.u32 %0, [%1];" : "=r"(v) : "l"(p) : "memory");
    return v;
}

__global__ __launch_bounds__(BD, 6) void fused_kernel(
    const float* __restrict__ hs,
    const float* __restrict__ x,
    const float* __restrict__ W,
    const float* __restrict__ bias,
    float* __restrict__ out_fused,
    float* __restrict__ out_xnorm)
{
    const int cta = blockIdx.x;
    const int tid = threadIdx.x;

    if (cta < SERIES_CTAS) {
        // ================= series branch (20 CTAs) ==========================
        const int sid = cta;
        const int d   = sid * BD + tid;

        __shared__ float sx[B_SZ * C_SZ * T_SZ];
        __shared__ float smn[B_SZ * C_SZ], smx[B_SZ * C_SZ];
        __shared__ float s_sm[B_SZ * T_SZ];
        __shared__ float sred[8][B_SZ];

        const int TOT = B_SZ * C_SZ * T_SZ;       // 2520
        for (int i = tid; i < TOT; i += BD) sx[i] = x[i];
        __syncthreads();

        if (tid < B_SZ * C_SZ) {
            const float* row = sx + tid * T_SZ;
            float mn = row[0], mx = row[0];
            #pragma unroll
            for (int t = 1; t < T_SZ; t++) {
                float v = row[t];
                mn = fminf(mn, v); mx = fmaxf(mx, v);
            }
            smn[tid] = mn; smx[tid] = mx;
        }
        __syncthreads();

        if (sid == 0) {
            for (int i = tid; i < TOT; i += BD) {
                int bc = i / T_SZ;
                float v = sx[i], mn = smn[bc], mx = smx[bc];
                out_xnorm[i] = (mx > mn) ? (v - mn) / (mx - mn) : v;
            }
        }

        for (int i = tid; i < B_SZ * T_SZ; i += BD) {
            int b = i / T_SZ, t = i % T_SZ;
            float s = 0.f;
            #pragma unroll
            for (int c = 0; c < C_SZ; c++)
                s += sx[(b * C_SZ + c) * T_SZ + t];
            s_sm[i] = s * (1.0f / (float)C_SZ);
        }
        __syncthreads();

        const float bv = bias[d];
        const int warp = tid >> 5, lane = tid & 31;

        #pragma unroll
        for (int g = 0; g < 2; g++) {
            float acc0 = bv, acc1 = bv, acc2 = bv, acc3 = bv;
            const float* m0 = s_sm + (g * 4 + 0) * T_SZ;
            const float* m1 = s_sm + (g * 4 + 1) * T_SZ;
            const float* m2 = s_sm + (g * 4 + 2) * T_SZ;
            const float* m3 = s_sm + (g * 4 + 3) * T_SZ;
            #pragma unroll
            for (int t = 0; t < T_SZ; t++) {
                const float w = W[(size_t)t * D_SZ + d];
                acc0 = fmaf(m0[t], w, acc0);
                acc1 = fmaf(m1[t], w, acc1);
                acc2 = fmaf(m2[t], w, acc2);
                acc3 = fmaf(m3[t], w, acc3);
            }
            g_emb[(size_t)(g * 4 + 0) * D_SZ + d] = acc0;
            g_emb[(size_t)(g * 4 + 1) * D_SZ + d] = acc1;
            g_emb[(size_t)(g * 4 + 2) * D_SZ + d] = acc2;
            g_emb[(size_t)(g * 4 + 3) * D_SZ + d] = acc3;

            const float sq[4] = {acc0 * acc0, acc1 * acc1, acc2 * acc2, acc3 * acc3};
            #pragma unroll
            for (int j = 0; j < 4; j++) {
                float v = sq[j];
                #pragma unroll
                for (int off = 16; off; off >>= 1)
                    v += __shfl_xor_sync(0xffffffffu, v, off);
                if (lane == 0) sred[warp][g * 4 + j] = v;
            }
            __syncthreads();
            if (tid < 4) {
                int b = g * 4 + tid;
                float tot = 0.f;
                #pragma unroll
                for (int w2 = 0; w2 < 8; w2++) tot += sred[w2][b];
                g_ssq_part[sid * B_SZ + b] = tot;
            }
            __syncthreads();
        }

        if (tid == 0) atom_add_acqrel_gpu(&g_series_done, 1u);
    } else {
        // ================= streaming CTAs (840, hybrid static+steal) ========
        const int scta   = cta - SERIES_CTAS;
        const int group  = scta % N_GROUPS;       // (b, dchunk)
        const int rank   = scta / N_GROUPS;       // 0..20: partial slot
        const int dchunk = group % 5;
        const int b      = group / 5;
        const int d4     = dchunk * BD + tid;

        const float4* base = reinterpret_cast<const float4*>(hs)
                           + (size_t)b * S_SZ * D4_SZ + d4;

        float4 a0 = make_float4(0.f, 0.f, 0.f, 0.f);
        float4 a1 = make_float4(0.f, 0.f, 0.f, 0.f);

        // ---- phase 1: static 168 rows, pure stream (zero sync) -------------
        {
            const float4* p = base + (size_t)(rank * STATIC_ROWS_PER_CTA) * D4_SZ;
            #pragma unroll 4
            for (int r = 0; r < STATIC_ROWS_PER_CTA; r += 2) {
                float4 v0 = __ldcs(p + (size_t)(r + 0) * D4_SZ);
                float4 v1 = __ldcs(p + (size_t)(r + 1) * D4_SZ);
                a0.x += v0.x; a0.y += v0.y; a0.z += v0.z; a0.w += v0.w;
                a1.x += v1.x; a1.y += v1.y; a1.z += v1.z; a1.w += v1.w;
            }
        }

        // ---- phase 2: steal remaining 71 chunks (absorbs spread) -----------
        {
            __shared__ unsigned s_next[2];
            if (tid == 0) s_next[0] = atomicAdd(&g_next[group], 1u);
            __syncthreads();

            int par = 0;
            for (;;) {
                const unsigned ck = s_next[par];
                if (ck >= STEAL_CHUNKS) break;
                if (tid == 0) s_next[par ^ 1] = atomicAdd(&g_next[group], 1u);

                const float4* p = base
                    + (size_t)(STATIC_ROWS + ck * CHUNK_ROWS) * D4_SZ;
                #pragma unroll
                for (int r = 0; r < CHUNK_ROWS; r += 2) {
                    float4 v0 = __ldcs(p + (size_t)(r + 0) * D4_SZ);
                    float4 v1 = __ldcs(p + (size_t)(r + 1) * D4_SZ);
                    a0.x += v0.x; a0.y += v0.y; a0.z += v0.z; a0.w += v0.w;
                    a1.x += v1.x; a1.y += v1.y; a1.z += v1.z; a1.w += v1.w;
                }
                __syncthreads();
                par ^= 1;
            }
        }

        float4 out;
        out.x = a0.x + a1.x; out.y = a0.y + a1.y;
        out.z = a0.z + a1.z; out.w = a0.w + a1.w;
        g_part[((size_t)rank * B_SZ + b) * D4_SZ + d4] = out;

        // arrival: one barrier orders all warps' STGs; thread 0 release-bumps
        __shared__ bool s_last;
        __syncthreads();
        if (tid == 0) {
            unsigned old = atom_add_acqrel_gpu(&g_cnt[group], 1u);
            s_last = (old == SPLITS - 1);
        }
        __syncthreads();

        if (s_last) {
            // ---- finisher: reduce 21 partials for this (b, dchunk) --------
            __shared__ float s_inv;
            if (tid == 0) {
                while (ld_acquire_gpu(&g_series_done) < SERIES_CTAS)
                    __nanosleep(64);
                float ssq = 0.f;
                #pragma unroll
                for (int s = 0; s < SERIES_CTAS; s++)
                    ssq += __ldcg(&g_ssq_part[s * B_SZ + b]);
                s_inv = 1.0f / fmaxf(sqrtf(ssq), 1e-12f);
            }
            __syncthreads();

            const float4* gp = g_part + (size_t)b * D4_SZ + d4;
            float4 acc = make_float4(0.f, 0.f, 0.f, 0.f);
            #pragma unroll
            for (int rr = 0; rr < SPLITS; rr++) {
                float4 v = __ldcg(gp + (size_t)rr * (B_SZ * D4_SZ));
                acc.x += v.x; acc.y += v.y; acc.z += v.z; acc.w += v.w;
            }

            const float inv  = s_inv;
            const float invS = 1.0f / (float)S_SZ;
            const float* e = g_emb + (size_t)b * D_SZ + (size_t)d4 * 4;
            float e0 = __ldcg(e + 0), e1 = __ldcg(e + 1);
            float e2 = __ldcg(e + 2), e3 = __ldcg(e + 3);

            float4 o;
            o.x = fmaf(e0, inv, acc.x * invS);
            o.y = fmaf(e1, inv, acc.y * invS);
            o.z = fmaf(e2, inv, acc.z * invS);
            o.w = fmaf(e3, inv, acc.w * invS);
            reinterpret_cast<float4*>(out_fused)[(size_t)b * D4_SZ + d4] = o;

            // reset scratch for the next graph replay
            __syncthreads();
            if (tid == 0) {
                g_cnt[group]  = 0u;
                g_next[group] = 0u;
                unsigned f = atom_add_acqrel_gpu(&g_fin, 1u);
                if (f == N_GROUPS - 1) {      // globally last finisher
                    g_series_done = 0u;
                    g_fin = 0u;
                }
            }
        }
    }
}

// ============================================================================
extern "C" void kernel_launch(void* const* d_in, const int* in_sizes, int n_in,
                              void* d_out, int out_size)
{
    const float* x    = (const float*)d_in[0];
    const float* hs   = (const float*)d_in[1];
    const float* W    = (const float*)d_in[2];
    const float* bias = (const float*)d_in[3];

    float* out_fused = (float*)d_out;                       // [B, D]
    float* out_xnorm = (float*)d_out + (size_t)B_SZ * D_SZ; // [B, C, T]

    fused_kernel<<<TOTAL_CTAS, BD>>>(hs, x, W, bias, out_fused, out_xnorm);
}